// round 17
// baseline (speedup 1.0000x reference)
#include <cuda_runtime.h>
#include <cuda_fp16.h>
#include <cstdint>

#define R 4096
#define F 256
#define K 8
#define CMIN 1e-6f
#define CMAX 1e6f
#define C_BIAS 0.5287663729448977f  /* log2(log2(e)) */

#define BM 128
#define BN 128
#define TILE_B 16384               // one 128row x 128B fp16 tile (BK=64)
#define A_SMEM (4 * TILE_B + 1024) // double-buffered A+B tiles

// Scratch (static device globals — no runtime allocation)
__device__ __align__(16) float g_base[(size_t)R * (size_t)R];  // na>1 path
__device__ __align__(16) __half g_num[(size_t)R * (size_t)R];  // na==1 path
__device__ __align__(16) float g_S[K * R];
__device__ __align__(16) float g_rs[4 * R];     // sx1 | n2x1 | sx2 | n2x2
__device__ __align__(16) float g_kc[5 * K];     // compacted: akt|bkt2|ekc2|hi|nw
__device__ int g_nact;
__device__ __align__(16) __half g_x1h[R * F];
__device__ __align__(16) __half g_x2h[R * F];

__device__ __forceinline__ uint32_t smem_u32(const void* p) {
    uint32_t a;
    asm("{ .reg .u64 t; cvta.to.shared.u64 t, %1; cvt.u32.u64 %0, t; }"
        : "=r"(a) : "l"(p));
    return a;
}
__device__ __forceinline__ float ex2f(float x) {
    float y;
    asm("ex2.approx.ftz.f32 %0, %1;" : "=f"(y) : "f"(x));
    return y;
}
__device__ __forceinline__ void ldsm_x4(uint32_t* r, uint32_t addr) {
    asm volatile("ldmatrix.sync.aligned.m8n8.x4.shared.b16 {%0,%1,%2,%3}, [%4];"
                 : "=r"(r[0]), "=r"(r[1]), "=r"(r[2]), "=r"(r[3]) : "r"(addr));
}
// fp16 x fp16 -> fp16 accumulate (2 regs = 4 halves; reg0 = row r cols c,c+1,
// reg1 = row r+8 cols c,c+1 — same positions as the fp32 c0..c3 layout)
__device__ __forceinline__ void mma16816h(uint32_t* c, const uint32_t* a,
                                          uint32_t b0, uint32_t b1) {
    asm volatile(
        "mma.sync.aligned.m16n8k16.row.col.f16.f16.f16.f16 "
        "{%0,%1}, {%2,%3,%4,%5}, {%6,%7}, {%0,%1};"
        : "+r"(c[0]), "+r"(c[1])
        : "r"(a[0]), "r"(a[1]), "r"(a[2]), "r"(a[3]), "r"(b0), "r"(b1));
}
__device__ __forceinline__ void cp16(uint32_t dst, const void* src) {
    asm volatile("cp.async.cg.shared.global [%0], [%1], 16;"
                 :: "r"(dst), "l"(src) : "memory");
}
#define CP_COMMIT() asm volatile("cp.async.commit_group;" ::: "memory")
#define CP_WAIT(n)  asm volatile("cp.async.wait_group %0;" :: "n"(n) : "memory")

// ---------------------------------------------------------------------------
// Fused prep: thread 0 computes compacted per-k constants (softmax weights
// > 1e-7 kept). All blocks: zero g_S; one warp per row: fp16 rounding +
// row sum + squared norm.
__global__ void __launch_bounds__(256)
prep_kernel(const float* __restrict__ x1, const float* __restrict__ x2,
            const float* __restrict__ sig, const float* __restrict__ mean,
            const float* __restrict__ sp) {
    const int gid = blockIdx.x * blockDim.x + threadIdx.x;
    if (gid == 0) {
        const float L2E = 1.4426950408889634f;
        float w[K];
        float m = -3.4e38f;
        #pragma unroll
        for (int k = 0; k < K; k++) {
            float v = 1.0f / (sp[k] * sp[k]);
            w[k] = v;
            if (v > m) m = v;
        }
        float s = 0.0f;
        #pragma unroll
        for (int k = 0; k < K; k++) { w[k] = __expf(w[k] - m); s += w[k]; }
        float inv_s = 1.0f / s;
        int na = 0;
        for (int k = 0; k < K; k++) {
            float nw = w[k] * inv_s;
            if (nw > 1e-7f) {
                float ekc2 = -L2E / (2.0f * sig[k] * sig[k]);
                float ak   = -2.0f * mean[k];
                float bk   = (float)F * mean[k] * mean[k];
                g_kc[na]         = ak * ekc2;              // akt
                g_kc[K + na]     = bk * ekc2 + C_BIAS;     // bkt2
                g_kc[2 * K + na] = ekc2;
                g_kc[3 * K + na] = CMIN * ekc2 + C_BIAS;   // hi clamp
                g_kc[4 * K + na] = nw;                     // weight
                na++;
            }
        }
        g_nact = na;
    }
    if (gid < K * R) g_S[gid] = 0.0f;

    const int w    = gid >> 5;
    const int lane = gid & 31;
    const bool is1 = (w < R);
    const int row  = is1 ? w : (w - R);
    const float* x = is1 ? x1 : x2;
    __half* xh = is1 ? g_x1h : g_x2h;

    const float* p = x + (size_t)row * F + lane * 8;
    float4 v0 = *(const float4*)p;
    float4 v1 = *(const float4*)(p + 4);
    float vals[8] = {v0.x, v0.y, v0.z, v0.w, v1.x, v1.y, v1.z, v1.w};

    float s = 0.0f, q = 0.0f;
    __half hb[8];
    #pragma unroll
    for (int e = 0; e < 8; e++) {
        float v = vals[e];
        s += v;
        q = fmaf(v, v, q);
        hb[e] = __float2half_rn(v);
    }
    *(uint4*)(xh + (size_t)row * F + lane * 8) = *(const uint4*)hb;

    #pragma unroll
    for (int o = 16; o > 0; o >>= 1) {
        s += __shfl_xor_sync(0xFFFFFFFFu, s, o);
        q += __shfl_xor_sync(0xFFFFFFFFu, q, o);
    }
    if (lane == 0) {
        int off = is1 ? 0 : 2 * R;
        g_rs[off + row]     = s;
        g_rs[off + R + row] = q;
    }
}

// ---------------------------------------------------------------------------
// Kernel A: 128x128 tile, single-pass fp16 GEMM (fp16 accumulate) via
// mma.sync m16n8k16, cp.async double-buffered k-loop. 8 warps 2(m) x 4(n).
// Epilogue: fp16 numerator storage when nact==1, else fp32 base + S.
__global__ void __launch_bounds__(256, 2)
kernelA() {
    extern __shared__ char dynsmem[];
    __shared__ float skc[5 * K];
    __shared__ int s_na;

    const int tid  = threadIdx.x;
    const int wid  = tid >> 5;
    const int lane = tid & 31;
    const int wm = wid & 1;          // m position -> 64 rows
    const int wn = wid >> 1;         // n position -> 32 cols
    const int ln15 = lane & 15;
    const int hi16 = lane >> 4;
    const int r0 = blockIdx.y * BM;
    const int c0 = blockIdx.x * BN;

    const uint32_t dsb = smem_u32(dynsmem);
    const uint32_t tiles_u = (dsb + 1023u) & ~1023u;

    if (tid < 5 * K) skc[tid] = g_kc[tid];
    if (tid == 0) s_na = g_nact;

    // loader mapping: 128 rows x 64 fp16 tiles, SW128 swizzle
    const int lrow  = tid >> 1;
    const int lcol0 = (tid & 1) * 32;
    const __half* pah = g_x1h + (size_t)(r0 + lrow) * F + lcol0;
    const __half* pbh = g_x2h + (size_t)(c0 + lrow) * F + lcol0;

    uint32_t swo[4];
    #pragma unroll
    for (int j = 0; j < 4; j++) {
        uint32_t boff = lrow * 128 + (lcol0 + j * 8) * 2;
        swo[j] = boff ^ ((boff >> 3) & 0x70);
    }

    const uint32_t a_row = (uint32_t)(wm * 64 + ln15) * 128u;
    const uint32_t b_row = (uint32_t)(wn * 32 + ln15) * 128u;

    uint32_t acc[4][4][2];
    #pragma unroll
    for (int i = 0; i < 4; i++)
        #pragma unroll
        for (int j = 0; j < 4; j++) { acc[i][j][0] = 0u; acc[i][j][1] = 0u; }

    // prologue: prefetch chunks 0 and 1
    #pragma unroll
    for (int pc = 0; pc < 2; pc++) {
        const uint32_t ab = tiles_u + pc * 2 * TILE_B;
        const int k0 = pc * 64;
        #pragma unroll
        for (int j = 0; j < 4; j++) {
            cp16(ab + swo[j], pah + k0 + j * 8);
            cp16(ab + TILE_B + swo[j], pbh + k0 + j * 8);
        }
        CP_COMMIT();
    }

    for (int kc = 0; kc < 4; kc++) {
        if (kc < 2) { CP_WAIT(1); } else { CP_WAIT(0); }
        __syncthreads();

        const uint32_t bufo = (uint32_t)(kc & 1) * 2 * TILE_B;
        const uint32_t ah_base = tiles_u + bufo + a_row;
        const uint32_t bh_base = tiles_u + bufo + TILE_B + b_row;

        #pragma unroll
        for (int ks = 0; ks < 4; ks++) {
            const uint32_t q = (uint32_t)(((ks * 2 + hi16) ^ (ln15 & 7)) * 16);
            uint32_t ah[4][4], bh[2][4];
            #pragma unroll
            for (int mf = 0; mf < 4; mf++)
                ldsm_x4(ah[mf], ah_base + q + mf * 2048);
            #pragma unroll
            for (int n2 = 0; n2 < 2; n2++)
                ldsm_x4(bh[n2], bh_base + q + n2 * 2048);

            #pragma unroll
            for (int mf = 0; mf < 4; mf++)
                #pragma unroll
                for (int nf = 0; nf < 4; nf++)
                    mma16816h(acc[mf][nf], ah[mf],
                              bh[nf >> 1][nf & 1], bh[nf >> 1][(nf & 1) + 2]);
        }
        __syncthreads();

        if (kc + 2 < 4) {
            const uint32_t ab = tiles_u + (uint32_t)(kc & 1) * 2 * TILE_B;
            const int k0 = (kc + 2) * 64;
            #pragma unroll
            for (int j = 0; j < 4; j++) {
                cp16(ab + swo[j], pah + k0 + j * 8);
                cp16(ab + TILE_B + swo[j], pbh + k0 + j * 8);
            }
            CP_COMMIT();
        }
    }

    // ---- epilogue ----
    // elem (mf, nf, half, e): row = r0 + wm*64 + mf*16 + half*8 + lane/4
    //                         col = c0 + wn*32 + nf*8 + (lane&3)*2 + e
    const int rbase = r0 + wm * 64 + (lane >> 2);
    const int cbase = c0 + wn * 32 + (lane & 3) * 2;

    float sx1r8[8], n21r8[8];
    #pragma unroll
    for (int i = 0; i < 8; i++) {
        int row = rbase + (i >> 1) * 16 + (i & 1) * 8;
        sx1r8[i] = g_rs[row];
        n21r8[i] = g_rs[R + row];
    }
    float n22c[8], s2c[8];
    #pragma unroll
    for (int nf = 0; nf < 4; nf++) {
        float2 n2 = *(const float2*)&g_rs[3 * R + cbase + nf * 8];
        float2 s2 = *(const float2*)&g_rs[2 * R + cbase + nf * 8];
        n22c[nf * 2] = n2.x; n22c[nf * 2 + 1] = n2.y;
        s2c[nf * 2]  = s2.x; s2c[nf * 2 + 1]  = s2.y;
    }

    // unpack fp16 accumulators and transform to base
    float bacc[4][4][4];
    #pragma unroll
    for (int mf = 0; mf < 4; mf++)
        #pragma unroll
        for (int h = 0; h < 2; h++) {
            float n21 = n21r8[mf * 2 + h];
            #pragma unroll
            for (int nf = 0; nf < 4; nf++) {
                float2 f = __half22float2(*(__half2*)&acc[mf][nf][h]);
                bacc[mf][nf][h * 2]     = n21 + n22c[nf * 2]     - 2.0f * f.x;
                bacc[mf][nf][h * 2 + 1] = n21 + n22c[nf * 2 + 1] - 2.0f * f.y;
            }
        }

    const int na = s_na;
    if (na == 1) {
        // store numerators e^kv as fp16; kernelB becomes a row-scale pass
        const float akt  = skc[0];
        const float nakt = -akt;
        const float bkt2 = skc[K];
        const float ekc2 = skc[2 * K];
        const float hi   = skc[3 * K];
        #pragma unroll
        for (int mf = 0; mf < 4; mf++)
            #pragma unroll
            for (int h = 0; h < 2; h++) {
                const float pi = fmaf(sx1r8[mf * 2 + h], akt, bkt2);
                float s = 0.0f;
                #pragma unroll
                for (int nf = 0; nf < 4; nf++)
                    #pragma unroll
                    for (int e = 0; e < 2; e++) {
                        int idx = h * 2 + e;
                        float arg = fmaf(bacc[mf][nf][idx], ekc2,
                                         fmaf(s2c[nf * 2 + e], nakt, pi));
                        arg = fminf(arg, hi);
                        float kv = ex2f(ex2f(arg));
                        bacc[mf][nf][idx] = kv;
                        s += kv;
                    }
                int row = rbase + mf * 16 + h * 8;
                __half* np = g_num + (size_t)row * R + cbase;
                #pragma unroll
                for (int nf = 0; nf < 4; nf++) {
                    __half2 hv = __floats2half2_rn(bacc[mf][nf][h * 2],
                                                   bacc[mf][nf][h * 2 + 1]);
                    *(__half2*)(np + nf * 8) = hv;
                }
                s += __shfl_xor_sync(0xFFFFFFFFu, s, 1);
                s += __shfl_xor_sync(0xFFFFFFFFu, s, 2);
                if ((lane & 3) == 0)
                    atomicAdd(&g_S[row], s);
            }
    } else {
        #pragma unroll
        for (int mf = 0; mf < 4; mf++)
            #pragma unroll
            for (int h = 0; h < 2; h++) {
                int row = rbase + mf * 16 + h * 8;
                #pragma unroll
                for (int nf = 0; nf < 4; nf++) {
                    float2 o = {bacc[mf][nf][h * 2], bacc[mf][nf][h * 2 + 1]};
                    *(float2*)&g_base[(size_t)row * R + cbase + nf * 8] = o;
                }
            }
        for (int kk = 0; kk < na; kk++) {
            const float akt  = skc[kk];
            const float nakt = -akt;
            const float bkt2 = skc[K + kk];
            const float ekc2 = skc[2 * K + kk];
            const float hi   = skc[3 * K + kk];
            #pragma unroll
            for (int mf = 0; mf < 4; mf++)
                #pragma unroll
                for (int h = 0; h < 2; h++) {
                    const float pi = fmaf(sx1r8[mf * 2 + h], akt, bkt2);
                    float s = 0.0f;
                    #pragma unroll
                    for (int nf = 0; nf < 4; nf++)
                        #pragma unroll
                        for (int e = 0; e < 2; e++) {
                            float arg = fmaf(bacc[mf][nf][h * 2 + e], ekc2,
                                             fmaf(s2c[nf * 2 + e], nakt, pi));
                            arg = fminf(arg, hi);
                            s += ex2f(ex2f(arg));
                        }
                    s += __shfl_xor_sync(0xFFFFFFFFu, s, 1);
                    s += __shfl_xor_sync(0xFFFFFFFFu, s, 2);
                    if ((lane & 3) == 0)
                        atomicAdd(&g_S[kk * R + rbase + mf * 16 + h * 8], s);
                }
        }
    }
}

// ---------------------------------------------------------------------------
// Kernel B: FOUR rows per block (more loads in flight). nact==1: row-scale
// of fp16 numerators. Otherwise recompute from fp32 base (double-ex2).
__global__ void __launch_bounds__(256)
kernelB(float* __restrict__ out) {
    const int r0 = blockIdx.x * 4;
    __shared__ float sa[K], se[K], shi[K];
    __shared__ float swgt[4 * K], sprm[4 * K];
    __shared__ int s_na;
    if (threadIdx.x == 0) s_na = g_nact;
    if (threadIdx.x < K) {
        int k = threadIdx.x;
        sa[k]  = g_kc[k];
        se[k]  = g_kc[2 * K + k];
        shi[k] = g_kc[3 * K + k];
    }
    if (threadIdx.x < 4 * K) {
        int r = threadIdx.x / K, k = threadIdx.x % K;
        float akt = g_kc[k];
        swgt[threadIdx.x] = g_kc[4 * K + k] / g_S[k * R + r0 + r];
        sprm[threadIdx.x] = fmaf(g_rs[r0 + r], akt, g_kc[K + k]);
    }
    __syncthreads();

    const int na = s_na;

    if (na == 1) {
        float w[4] = {swgt[0], swgt[K], swgt[2 * K], swgt[3 * K]};
        #pragma unroll
        for (int r = 0; r < 4; r++) {
            const __half* nr = g_num + (size_t)(r0 + r) * R;
            float* orow = out + (size_t)(r0 + r) * R;
            #pragma unroll
            for (int it = 0; it < R / (256 * 8); it++) {
                int c = (it * 256 + threadIdx.x) * 8;
                uint4 hv = *(const uint4*)(nr + c);
                const __half2* ph = (const __half2*)&hv;
                float o[8];
                #pragma unroll
                for (int q = 0; q < 4; q++) {
                    float2 f = __half22float2(ph[q]);
                    o[q * 2]     = f.x * w[r];
                    o[q * 2 + 1] = f.y * w[r];
                }
                *(float4*)(orow + c)     = *(float4*)&o[0];
                *(float4*)(orow + c + 4) = *(float4*)&o[4];
            }
        }
        return;
    }

    #pragma unroll
    for (int r = 0; r < 4; r++) {
        const float* brow = g_base + (size_t)(r0 + r) * R;
        float* orow = out + (size_t)(r0 + r) * R;
        #pragma unroll
        for (int it = 0; it < R / (256 * 4); it++) {
            int c = (it * 256 + threadIdx.x) * 4;
            float4 s4 = *(const float4*)(g_rs + 2 * R + c);
            float4 b4 = *(const float4*)(brow + c);
            const float* cc = (const float*)&s4;
            const float* bb = (const float*)&b4;
            float o[4] = {0.0f, 0.0f, 0.0f, 0.0f};
            for (int kk = 0; kk < na; kk++) {
                const float nakt = -sa[kk];
                const float ekc2 = se[kk];
                const float hi   = shi[kk];
                const float wk   = swgt[r * K + kk];
                const float pr   = sprm[r * K + kk];
                #pragma unroll
                for (int j = 0; j < 4; j++) {
                    float a = fmaf(bb[j], ekc2, fmaf(cc[j], nakt, pr));
                    a = fminf(a, hi);
                    o[j] = fmaf(ex2f(ex2f(a)), wk, o[j]);
                }
            }
            float4 ov = {o[0], o[1], o[2], o[3]};
            *(float4*)(orow + c) = ov;
        }
    }
}

// ---------------------------------------------------------------------------
extern "C" void kernel_launch(void* const* d_in, const int* in_sizes, int n_in,
                              void* d_out, int out_size) {
    const float* x1   = (const float*)d_in[0];  // [R, F]
    const float* x2   = (const float*)d_in[1];  // [R, F]
    const float* sig  = (const float*)d_in[2];  // [K]
    const float* mean = (const float*)d_in[3];  // [K]
    const float* sp   = (const float*)d_in[4];  // [K]
    float* out = (float*)d_out;                 // [R, R]

    cudaFuncSetAttribute(kernelA, cudaFuncAttributeMaxDynamicSharedMemorySize,
                         A_SMEM);

    prep_kernel<<<(2 * R) / 8, 256>>>(x1, x2, sig, mean, sp);

    dim3 gridA(R / BN, R / BM);
    kernelA<<<gridA, 256, A_SMEM>>>();

    kernelB<<<R / 4, 256>>>(out);
}